// round 2
// baseline (speedup 1.0000x reference)
#include <cuda_runtime.h>
#include <math.h>

#define NN    8192
#define NFEAT 512
#define NHID  256
#define NCLS  2
#define ALPHA 0.5f

// ---------------- scratch (device globals; no allocation allowed) ----------
struct Scratch {
    float rowsum[NN];
    float colsum[NN];
    float drow[NN];
    float dcol[NN];
    float M [NN * NHID];   // x @ W1
    float Y1[NN * NHID];   // DAD @ M
    float Y2[NN * NHID];   // DAD @ Y1
    float Hh[NN * NHID];   // relu(a*M + (a-1)*Y1 - Y2)
    float V [NN * NCLS];   // Hh @ W2
    float Z1[NN * NCLS];   // DAD @ V
    float Z2[NN * NCLS];   // DAD @ Z1
};
__device__ Scratch g_s;

// ---------------- small utility kernels ------------------------------------
__global__ void k_zero(float* __restrict__ p, int n) {
    int i = blockIdx.x * blockDim.x + threadIdx.x;
    if (i < n) p[i] = 0.0f;
}

// row sums: one block per row, vectorized
__global__ void __launch_bounds__(256) k_rowsum(const float* __restrict__ adj,
                                                float* __restrict__ rowsum) {
    int row = blockIdx.x;
    const float* a = adj + (size_t)row * NN;
    float acc = 0.0f;
    for (int j = threadIdx.x * 4; j < NN; j += blockDim.x * 4) {
        float4 v = *(const float4*)(a + j);
        acc += v.x + v.y + v.z + v.w;
    }
    __shared__ float sh[256];
    sh[threadIdx.x] = acc;
    __syncthreads();
    for (int st = 128; st > 0; st >>= 1) {
        if (threadIdx.x < st) sh[threadIdx.x] += sh[threadIdx.x + st];
        __syncthreads();
    }
    if (threadIdx.x == 0) rowsum[row] = sh[0];
}

// col sums: tile (128 rows x 256 cols) per block, atomic partials
__global__ void __launch_bounds__(256) k_colsum(const float* __restrict__ adj,
                                                float* __restrict__ colsum) {
    int col = blockIdx.x * 256 + threadIdx.x;
    size_t r0 = (size_t)blockIdx.y * 128;
    float acc = 0.0f;
#pragma unroll 4
    for (int r = 0; r < 128; r++) {
        acc += adj[(r0 + r) * NN + col];
    }
    atomicAdd(&colsum[col], acc);
}

__global__ void k_rsqrt(const float* __restrict__ rowsum, const float* __restrict__ colsum,
                        float* __restrict__ drow, float* __restrict__ dcol) {
    int i = blockIdx.x * blockDim.x + threadIdx.x;
    if (i < NN) {
        float r = rowsum[i];
        float c = colsum[i];
        drow[i] = (r > 0.0f) ? rsqrtf(r) : 0.0f;
        dcol[i] = (c > 0.0f) ? rsqrtf(c) : 0.0f;
    }
}

// ---------------- tiled SGEMM: C = rowscale ⊙ (A @ (colscale ⊙rows B)) -----
// A: M x K row-major, B: K x N row-major, C: M x N row-major.
// colscale[k] scales B row k (fused DAD right-scaling), rowscale[m] scales C row.
#define BM 128
#define BN 128
#define BKK 8
#define TM 8
#define TN 8

template <bool RS, bool CS>
__global__ void __launch_bounds__(256) k_sgemm(const float* __restrict__ A,
                                               const float* __restrict__ B,
                                               float* __restrict__ C,
                                               int Mm, int Nn, int Kk,
                                               const float* __restrict__ rowscale,
                                               const float* __restrict__ colscale) {
    __shared__ float As[BKK][BM];
    __shared__ float Bs[BKK][BN];

    int tid = threadIdx.x;
    int bx = blockIdx.x, by = blockIdx.y;

    // A tile load: 128x8, one float4 per thread
    int arow = tid >> 1;
    int acol = (tid & 1) * 4;
    // B tile load: 8x128, one float4 per thread
    int brow = tid >> 5;
    int bcol = (tid & 31) * 4;

    const float* Ap = A + (size_t)(by * BM + arow) * Kk + acol;
    const float* Bp = B + (size_t)brow * Nn + bx * BN + bcol;

    int tr = (tid >> 4) * TM;   // 0..120
    int tc = (tid & 15) * TN;   // 0..120

    float acc[TM][TN];
#pragma unroll
    for (int i = 0; i < TM; i++)
#pragma unroll
        for (int j = 0; j < TN; j++) acc[i][j] = 0.0f;

    for (int k0 = 0; k0 < Kk; k0 += BKK) {
        float4 av = *(const float4*)Ap;
        Ap += BKK;
        As[acol + 0][arow] = av.x;
        As[acol + 1][arow] = av.y;
        As[acol + 2][arow] = av.z;
        As[acol + 3][arow] = av.w;

        float4 bv = *(const float4*)Bp;
        Bp += (size_t)BKK * Nn;
        if (CS) {
            float cs = colscale[k0 + brow];
            bv.x *= cs; bv.y *= cs; bv.z *= cs; bv.w *= cs;
        }
        *(float4*)&Bs[brow][bcol] = bv;

        __syncthreads();

#pragma unroll
        for (int k = 0; k < BKK; k++) {
            float ar[TM], br[TN];
#pragma unroll
            for (int i = 0; i < TM; i++) ar[i] = As[k][tr + i];
#pragma unroll
            for (int j = 0; j < TN; j++) br[j] = Bs[k][tc + j];
#pragma unroll
            for (int i = 0; i < TM; i++)
#pragma unroll
                for (int j = 0; j < TN; j++) acc[i][j] = fmaf(ar[i], br[j], acc[i][j]);
        }
        __syncthreads();
    }

#pragma unroll
    for (int i = 0; i < TM; i++) {
        int row = by * BM + tr + i;
        float rs = RS ? rowscale[row] : 1.0f;
        float* Cp = C + (size_t)row * Nn + bx * BN + tc;
#pragma unroll
        for (int j = 0; j < TN; j += 4) {
            float4 v;
            v.x = acc[i][j + 0] * rs;
            v.y = acc[i][j + 1] * rs;
            v.z = acc[i][j + 2] * rs;
            v.w = acc[i][j + 3] * rs;
            *(float4*)(Cp + j) = v;
        }
    }
}

// H = relu(alpha*M + (alpha-1)*Y1 - Y2), elementwise, vectorized
__global__ void k_combineH(const float* __restrict__ M, const float* __restrict__ Y1,
                           const float* __restrict__ Y2, float* __restrict__ Hh) {
    int i = blockIdx.x * blockDim.x + threadIdx.x;
    int n4 = (NN * NHID) / 4;
    if (i < n4) {
        float4 m = ((const float4*)M)[i];
        float4 a = ((const float4*)Y1)[i];
        float4 b = ((const float4*)Y2)[i];
        float4 o;
        o.x = fmaxf(ALPHA * m.x + (ALPHA - 1.0f) * a.x - b.x, 0.0f);
        o.y = fmaxf(ALPHA * m.y + (ALPHA - 1.0f) * a.y - b.y, 0.0f);
        o.z = fmaxf(ALPHA * m.z + (ALPHA - 1.0f) * a.z - b.z, 0.0f);
        o.w = fmaxf(ALPHA * m.w + (ALPHA - 1.0f) * a.w - b.w, 0.0f);
        ((float4*)Hh)[i] = o;
    }
}

// V = H @ W2   (8192x256 @ 256x2): one warp per output row
__global__ void __launch_bounds__(256) k_hw2(const float* __restrict__ Hh,
                                             const float* __restrict__ W2,
                                             float* __restrict__ V) {
    int warp = threadIdx.x >> 5;
    int lane = threadIdx.x & 31;
    int row = blockIdx.x * 8 + warp;
    const float* h = Hh + (size_t)row * NHID;
    float a0 = 0.0f, a1 = 0.0f;
#pragma unroll
    for (int j = lane; j < NHID; j += 32) {
        float hv = h[j];
        a0 = fmaf(hv, W2[2 * j + 0], a0);
        a1 = fmaf(hv, W2[2 * j + 1], a1);
    }
#pragma unroll
    for (int o = 16; o > 0; o >>= 1) {
        a0 += __shfl_down_sync(0xffffffffu, a0, o);
        a1 += __shfl_down_sync(0xffffffffu, a1, o);
    }
    if (lane == 0) {
        V[2 * row + 0] = a0;
        V[2 * row + 1] = a1;
    }
}

// out = drow ⊙ (adj @ (dcol ⊙rows v)), v is NN x 2. One block per row.
__global__ void __launch_bounds__(256) k_adjmv2(const float* __restrict__ adj,
                                                const float* __restrict__ v,
                                                const float* __restrict__ drow,
                                                const float* __restrict__ dcol,
                                                float* __restrict__ out) {
    int row = blockIdx.x;
    const float* a = adj + (size_t)row * NN;
    float a0 = 0.0f, a1 = 0.0f;
    for (int j = threadIdx.x; j < NN; j += 256) {
        float av = a[j];
        float c = dcol[j];
        float ac = av * c;
        a0 = fmaf(ac, v[2 * j + 0], a0);
        a1 = fmaf(ac, v[2 * j + 1], a1);
    }
    __shared__ float s0[256];
    __shared__ float s1[256];
    s0[threadIdx.x] = a0;
    s1[threadIdx.x] = a1;
    __syncthreads();
    for (int st = 128; st > 0; st >>= 1) {
        if (threadIdx.x < st) {
            s0[threadIdx.x] += s0[threadIdx.x + st];
            s1[threadIdx.x] += s1[threadIdx.x + st];
        }
        __syncthreads();
    }
    if (threadIdx.x == 0) {
        float r = drow[row];
        out[2 * row + 0] = r * s0[0];
        out[2 * row + 1] = r * s1[0];
    }
}

// logits = alpha*V + (alpha-1)*Z1 - Z2 + b2;  out = log_softmax(logits)
__global__ void k_final(const float* __restrict__ V, const float* __restrict__ Z1,
                        const float* __restrict__ Z2, const float* __restrict__ b2,
                        float* __restrict__ out) {
    int i = blockIdx.x * blockDim.x + threadIdx.x;
    if (i < NN) {
        float l0 = ALPHA * V[2 * i + 0] + (ALPHA - 1.0f) * Z1[2 * i + 0] - Z2[2 * i + 0] + b2[0];
        float l1 = ALPHA * V[2 * i + 1] + (ALPHA - 1.0f) * Z1[2 * i + 1] - Z2[2 * i + 1] + b2[1];
        float m = fmaxf(l0, l1);
        float lse = m + logf(expf(l0 - m) + expf(l1 - m));
        out[2 * i + 0] = l0 - lse;
        out[2 * i + 1] = l1 - lse;
    }
}

// ---------------- launcher --------------------------------------------------
extern "C" void kernel_launch(void* const* d_in, const int* in_sizes, int n_in,
                              void* d_out, int out_size) {
    // identify inputs by element count (robust to ordering)
    const float *x = nullptr, *adj = nullptr, *W1 = nullptr, *W2 = nullptr, *b2 = nullptr;
    for (int i = 0; i < n_in; i++) {
        switch (in_sizes[i]) {
            case NN * NFEAT:        x   = (const float*)d_in[i]; break;   // 4194304
            case (int)((size_t)NN * NN): adj = (const float*)d_in[i]; break; // 67108864
            case NFEAT * NHID:      W1  = (const float*)d_in[i]; break;   // 131072
            case NHID * NCLS:       W2  = (const float*)d_in[i]; break;   // 512
            case NCLS:              b2  = (const float*)d_in[i]; break;   // 2
        }
    }
    float* out = (float*)d_out;

    Scratch* s = nullptr;
    cudaGetSymbolAddress((void**)&s, g_s);

    // 1) degree vectors
    k_rowsum<<<NN, 256>>>(adj, s->rowsum);
    k_zero<<<(NN + 255) / 256, 256>>>(s->colsum, NN);
    k_colsum<<<dim3(NN / 256, NN / 128), 256>>>(adj, s->colsum);
    k_rsqrt<<<(NN + 255) / 256, 256>>>(s->rowsum, s->colsum, s->drow, s->dcol);

    // 2) M = x @ W1
    k_sgemm<false, false><<<dim3(NHID / BN, NN / BM), 256>>>(
        x, W1, s->M, NN, NHID, NFEAT, nullptr, nullptr);

    // 3) Y1 = DAD @ M ; Y2 = DAD @ Y1   (scaling fused into GEMM)
    k_sgemm<true, true><<<dim3(NHID / BN, NN / BM), 256>>>(
        adj, s->M, s->Y1, NN, NHID, NN, s->drow, s->dcol);
    k_sgemm<true, true><<<dim3(NHID / BN, NN / BM), 256>>>(
        adj, s->Y1, s->Y2, NN, NHID, NN, s->drow, s->dcol);

    // 4) H = relu(a*M + (a-1)*Y1 - Y2)
    k_combineH<<<(NN * NHID / 4 + 255) / 256, 256>>>(s->M, s->Y1, s->Y2, s->Hh);

    // 5) V = H @ W2
    k_hw2<<<NN / 8, 256>>>(s->Hh, W2, s->V);

    // 6) Z1 = DAD @ V ; Z2 = DAD @ Z1
    k_adjmv2<<<NN, 256>>>(adj, s->V, s->drow, s->dcol, s->Z1);
    k_adjmv2<<<NN, 256>>>(adj, s->Z1, s->drow, s->dcol, s->Z2);

    // 7) logits + log_softmax
    k_final<<<(NN + 255) / 256, 256>>>(s->V, s->Z1, s->Z2, b2, out);
}

// round 4
// speedup vs baseline: 2.9494x; 2.9494x over previous
#include <cuda_runtime.h>
#include <math.h>
#include <stdint.h>

#define NN    8192
#define NFEAT 512
#define NHID  256
#define NCLS  2
#define ALPHA 0.5f

// ---------------- scratch (device globals; no allocation allowed) ----------
struct Scratch {
    float rowsum[NN];
    float colsum[NN];
    float drow[NN];
    float dcol[NN];
    float M [NN * NHID];   // x @ W1
    float Y1[NN * NHID];   // DAD @ M
    float Y2[NN * NHID];   // DAD @ Y1
    float Hh[NN * NHID];   // relu(a*M + (a-1)*Y1 - Y2)
    float Bt[NN * NHID];   // tf32-rounded, dcol-scaled B operand
    float V [NN * NCLS];
    float Z1[NN * NCLS];
    float Z2[NN * NCLS];
};
__device__ Scratch g_s;
__device__ float g_adjt[(size_t)NN * NN];   // tf32-rounded copy of adj

// ---------------- helpers ---------------------------------------------------
__device__ __forceinline__ float to_tf32(float x) {
    float y;
    asm("cvt.rna.tf32.f32 %0, %1;" : "=f"(y) : "f"(x));
    return y;
}

__device__ __forceinline__ void cp_async16(void* smem_dst, const void* gmem_src) {
    uint32_t s = (uint32_t)__cvta_generic_to_shared(smem_dst);
    asm volatile("cp.async.cg.shared.global [%0], [%1], 16;\n" :: "r"(s), "l"(gmem_src));
}
#define CP_COMMIT()  asm volatile("cp.async.commit_group;\n" ::: "memory")
#define CP_WAIT(n)   asm volatile("cp.async.wait_group %0;\n" :: "n"(n) : "memory")

__device__ __forceinline__ void mma_tf32(float* d, const float* a, const float* b) {
    uint32_t a0 = __float_as_uint(a[0]), a1 = __float_as_uint(a[1]);
    uint32_t a2 = __float_as_uint(a[2]), a3 = __float_as_uint(a[3]);
    uint32_t b0 = __float_as_uint(b[0]), b1 = __float_as_uint(b[1]);
    asm volatile(
        "mma.sync.aligned.m16n8k8.row.col.f32.tf32.tf32.f32 "
        "{%0,%1,%2,%3}, {%4,%5,%6,%7}, {%8,%9}, {%0,%1,%2,%3};"
        : "+f"(d[0]), "+f"(d[1]), "+f"(d[2]), "+f"(d[3])
        : "r"(a0), "r"(a1), "r"(a2), "r"(a3), "r"(b0), "r"(b1));
}

// ---------------- small utility kernels ------------------------------------
__global__ void k_zero(float* __restrict__ p, int n) {
    int i = blockIdx.x * blockDim.x + threadIdx.x;
    if (i < n) p[i] = 0.0f;
}

__global__ void __launch_bounds__(256) k_rowsum(const float* __restrict__ adj,
                                                float* __restrict__ rowsum) {
    int row = blockIdx.x;
    const float* a = adj + (size_t)row * NN;
    float acc = 0.0f;
    for (int j = threadIdx.x * 4; j < NN; j += blockDim.x * 4) {
        float4 v = *(const float4*)(a + j);
        acc += v.x + v.y + v.z + v.w;
    }
    __shared__ float sh[256];
    sh[threadIdx.x] = acc;
    __syncthreads();
    for (int st = 128; st > 0; st >>= 1) {
        if (threadIdx.x < st) sh[threadIdx.x] += sh[threadIdx.x + st];
        __syncthreads();
    }
    if (threadIdx.x == 0) rowsum[row] = sh[0];
}

// col sums + write tf32-rounded copy of adj (single pass over adj)
__global__ void __launch_bounds__(256) k_colsum_cvt(const float* __restrict__ adj,
                                                    float* __restrict__ adjt,
                                                    float* __restrict__ colsum) {
    int col = blockIdx.x * 256 + threadIdx.x;
    size_t r0 = (size_t)blockIdx.y * 128;
    float acc = 0.0f;
#pragma unroll 4
    for (int r = 0; r < 128; r++) {
        size_t idx = (r0 + r) * NN + col;
        float v = adj[idx];
        acc += v;
        adjt[idx] = to_tf32(v);
    }
    atomicAdd(&colsum[col], acc);
}

__global__ void k_rsqrt(const float* __restrict__ rowsum, const float* __restrict__ colsum,
                        float* __restrict__ drow, float* __restrict__ dcol) {
    int i = blockIdx.x * blockDim.x + threadIdx.x;
    if (i < NN) {
        float r = rowsum[i];
        float c = colsum[i];
        drow[i] = (r > 0.0f) ? rsqrtf(r) : 0.0f;
        dcol[i] = (c > 0.0f) ? rsqrtf(c) : 0.0f;
    }
}

// Bt[k][n] = tf32(dcol[k] * B[k][n]),  B is NN x NHID
__global__ void k_prepB(const float* __restrict__ B, const float* __restrict__ dcol,
                        float* __restrict__ Bt) {
    int i = blockIdx.x * 256 + threadIdx.x;
    if (i < NN * NHID) {
        int k = i >> 8;   // / NHID
        Bt[i] = to_tf32(dcol[k] * B[i]);
    }
}

// ---------------- fp32 tiled SGEMM (kept for x @ W1) ------------------------
#define BM 128
#define BN 128
#define BKK 8
#define TM 8
#define TN 8

__global__ void __launch_bounds__(256) k_sgemm(const float* __restrict__ A,
                                               const float* __restrict__ B,
                                               float* __restrict__ C,
                                               int Nn, int Kk) {
    __shared__ float As[BKK][BM];
    __shared__ float Bs[BKK][BN];
    int tid = threadIdx.x;
    int bx = blockIdx.x, by = blockIdx.y;
    int arow = tid >> 1;
    int acol = (tid & 1) * 4;
    int brow = tid >> 5;
    int bcol = (tid & 31) * 4;
    const float* Ap = A + (size_t)(by * BM + arow) * Kk + acol;
    const float* Bp = B + (size_t)brow * Nn + bx * BN + bcol;
    int tr = (tid >> 4) * TM;
    int tc = (tid & 15) * TN;

    float acc[TM][TN];
#pragma unroll
    for (int i = 0; i < TM; i++)
#pragma unroll
        for (int j = 0; j < TN; j++) acc[i][j] = 0.0f;

    for (int k0 = 0; k0 < Kk; k0 += BKK) {
        float4 av = *(const float4*)Ap;
        Ap += BKK;
        As[acol + 0][arow] = av.x;
        As[acol + 1][arow] = av.y;
        As[acol + 2][arow] = av.z;
        As[acol + 3][arow] = av.w;
        float4 bv = *(const float4*)Bp;
        Bp += (size_t)BKK * Nn;
        *(float4*)&Bs[brow][bcol] = bv;
        __syncthreads();
#pragma unroll
        for (int k = 0; k < BKK; k++) {
            float ar[TM], br[TN];
#pragma unroll
            for (int i = 0; i < TM; i++) ar[i] = As[k][tr + i];
#pragma unroll
            for (int j = 0; j < TN; j++) br[j] = Bs[k][tc + j];
#pragma unroll
            for (int i = 0; i < TM; i++)
#pragma unroll
                for (int j = 0; j < TN; j++) acc[i][j] = fmaf(ar[i], br[j], acc[i][j]);
        }
        __syncthreads();
    }
#pragma unroll
    for (int i = 0; i < TM; i++) {
        int row = by * BM + tr + i;
        float* Cp = C + (size_t)row * Nn + bx * BN + tc;
#pragma unroll
        for (int j = 0; j < TN; j += 4) {
            float4 v;
            v.x = acc[i][j + 0];
            v.y = acc[i][j + 1];
            v.z = acc[i][j + 2];
            v.w = acc[i][j + 3];
            *(float4*)(Cp + j) = v;
        }
    }
}

// ---------------- TF32 tensor-core GEMM: C = drow ⊙ (A @ B) -----------------
// A: NN x NN (tf32-rounded), B: NN x NHID (tf32-rounded, dcol-scaled), row-major.
// Block 128 threads (4 warps, 2x2), tile 128x128, BK=16, 2-stage cp.async.
#define MT_BK 16
#define AS_STRIDE 20    // 128 rows x 20 floats (80B rows, 16B aligned, conflict-free)
#define BS_STRIDE 136   // 16 rows x 136 floats (544B rows, conflict-free)

__global__ void __launch_bounds__(128) k_mma_dad(const float* __restrict__ A,
                                                 const float* __restrict__ B,
                                                 float* __restrict__ C,
                                                 const float* __restrict__ rowscale) {
    __shared__ float As[2][128 * AS_STRIDE];
    __shared__ float Bs[2][MT_BK * BS_STRIDE];

    const int K = NN;
    int tid = threadIdx.x;
    int wid = tid >> 5, lane = tid & 31;
    int wm0 = (wid >> 1) * 64;
    int wn0 = (wid & 1) * 64;
    int bx = blockIdx.x;   // N block (0..1)
    int by = blockIdx.y;   // M block (0..63)

    const float* Ag = A + (size_t)by * 128 * K;
    const float* Bg = B + (size_t)bx * 128;   // B row stride = NHID

    float acc[4][8][4];
#pragma unroll
    for (int mt = 0; mt < 4; mt++)
#pragma unroll
        for (int nt = 0; nt < 8; nt++)
#pragma unroll
            for (int f = 0; f < 4; f++) acc[mt][nt][f] = 0.0f;

    int g = lane >> 2;      // 0..7
    int q = lane & 3;       // 0..3

    // ---- async tile loaders -------------------------------------------------
    auto loadA = [&](int buf, int k0) {
#pragma unroll
        for (int i = 0; i < 4; i++) {
            int c = i * 128 + tid;          // 512 chunks of 16B
            int row = c >> 2;
            int coff = (c & 3) * 4;
            cp_async16(&As[buf][row * AS_STRIDE + coff],
                       Ag + (size_t)row * K + k0 + coff);
        }
    };
    auto loadB = [&](int buf, int k0) {
#pragma unroll
        for (int i = 0; i < 4; i++) {
            int c = i * 128 + tid;          // 512 chunks of 16B
            int kr = c >> 5;
            int coff = (c & 31) * 4;
            cp_async16(&Bs[buf][kr * BS_STRIDE + coff],
                       Bg + (size_t)(k0 + kr) * NHID + coff);
        }
    };

    loadA(0, 0);
    loadB(0, 0);
    CP_COMMIT();

    int buf = 0;
#pragma unroll 1
    for (int k0 = 0; k0 < K; k0 += MT_BK) {
        if (k0 + MT_BK < K) {
            loadA(buf ^ 1, k0 + MT_BK);
            loadB(buf ^ 1, k0 + MT_BK);
            CP_COMMIT();
            CP_WAIT(1);
        } else {
            CP_WAIT(0);
        }
        __syncthreads();

#pragma unroll
        for (int ks = 0; ks < 2; ks++) {
            int kb = ks * 8;
            float afr[4][4];
#pragma unroll
            for (int mt = 0; mt < 4; mt++) {
                int r = wm0 + mt * 16 + g;
                afr[mt][0] = As[buf][r * AS_STRIDE + kb + q];
                afr[mt][1] = As[buf][(r + 8) * AS_STRIDE + kb + q];
                afr[mt][2] = As[buf][r * AS_STRIDE + kb + q + 4];
                afr[mt][3] = As[buf][(r + 8) * AS_STRIDE + kb + q + 4];
            }
            float bfr[8][2];
#pragma unroll
            for (int nt = 0; nt < 8; nt++) {
                int col = wn0 + nt * 8 + g;
                bfr[nt][0] = Bs[buf][(kb + q) * BS_STRIDE + col];
                bfr[nt][1] = Bs[buf][(kb + q + 4) * BS_STRIDE + col];
            }
#pragma unroll
            for (int mt = 0; mt < 4; mt++)
#pragma unroll
                for (int nt = 0; nt < 8; nt++)
                    mma_tf32(acc[mt][nt], afr[mt], bfr[nt]);
        }
        __syncthreads();
        buf ^= 1;
    }

    // ---- epilogue: scale by drow, write fp32 --------------------------------
#pragma unroll
    for (int mt = 0; mt < 4; mt++) {
        int r0 = by * 128 + wm0 + mt * 16 + g;
        float rs0 = rowscale[r0];
        float rs1 = rowscale[r0 + 8];
#pragma unroll
        for (int nt = 0; nt < 8; nt++) {
            int cc = bx * 128 + wn0 + nt * 8 + q * 2;
            float2 v0 = make_float2(acc[mt][nt][0] * rs0, acc[mt][nt][1] * rs0);
            float2 v1 = make_float2(acc[mt][nt][2] * rs1, acc[mt][nt][3] * rs1);
            *(float2*)(C + (size_t)r0 * NHID + cc) = v0;
            *(float2*)(C + (size_t)(r0 + 8) * NHID + cc) = v1;
        }
    }
}

// ---------------- remaining elementwise / narrow kernels --------------------
__global__ void k_combineH(const float* __restrict__ M, const float* __restrict__ Y1,
                           const float* __restrict__ Y2, float* __restrict__ Hh) {
    int i = blockIdx.x * blockDim.x + threadIdx.x;
    int n4 = (NN * NHID) / 4;
    if (i < n4) {
        float4 m = ((const float4*)M)[i];
        float4 a = ((const float4*)Y1)[i];
        float4 b = ((const float4*)Y2)[i];
        float4 o;
        o.x = fmaxf(ALPHA * m.x + (ALPHA - 1.0f) * a.x - b.x, 0.0f);
        o.y = fmaxf(ALPHA * m.y + (ALPHA - 1.0f) * a.y - b.y, 0.0f);
        o.z = fmaxf(ALPHA * m.z + (ALPHA - 1.0f) * a.z - b.z, 0.0f);
        o.w = fmaxf(ALPHA * m.w + (ALPHA - 1.0f) * a.w - b.w, 0.0f);
        ((float4*)Hh)[i] = o;
    }
}

__global__ void __launch_bounds__(256) k_hw2(const float* __restrict__ Hh,
                                             const float* __restrict__ W2,
                                             float* __restrict__ V) {
    int warp = threadIdx.x >> 5;
    int lane = threadIdx.x & 31;
    int row = blockIdx.x * 8 + warp;
    const float* h = Hh + (size_t)row * NHID;
    float a0 = 0.0f, a1 = 0.0f;
#pragma unroll
    for (int j = lane; j < NHID; j += 32) {
        float hv = h[j];
        a0 = fmaf(hv, W2[2 * j + 0], a0);
        a1 = fmaf(hv, W2[2 * j + 1], a1);
    }
#pragma unroll
    for (int o = 16; o > 0; o >>= 1) {
        a0 += __shfl_down_sync(0xffffffffu, a0, o);
        a1 += __shfl_down_sync(0xffffffffu, a1, o);
    }
    if (lane == 0) {
        V[2 * row + 0] = a0;
        V[2 * row + 1] = a1;
    }
}

__global__ void __launch_bounds__(256) k_adjmv2(const float* __restrict__ adj,
                                                const float* __restrict__ v,
                                                const float* __restrict__ drow,
                                                const float* __restrict__ dcol,
                                                float* __restrict__ out) {
    int row = blockIdx.x;
    const float* a = adj + (size_t)row * NN;
    float a0 = 0.0f, a1 = 0.0f;
    for (int j = threadIdx.x; j < NN; j += 256) {
        float ac = a[j] * dcol[j];
        a0 = fmaf(ac, v[2 * j + 0], a0);
        a1 = fmaf(ac, v[2 * j + 1], a1);
    }
    __shared__ float s0[256];
    __shared__ float s1[256];
    s0[threadIdx.x] = a0;
    s1[threadIdx.x] = a1;
    __syncthreads();
    for (int st = 128; st > 0; st >>= 1) {
        if (threadIdx.x < st) {
            s0[threadIdx.x] += s0[threadIdx.x + st];
            s1[threadIdx.x] += s1[threadIdx.x + st];
        }
        __syncthreads();
    }
    if (threadIdx.x == 0) {
        float r = drow[row];
        out[2 * row + 0] = r * s0[0];
        out[2 * row + 1] = r * s1[0];
    }
}

__global__ void k_final(const float* __restrict__ V, const float* __restrict__ Z1,
                        const float* __restrict__ Z2, const float* __restrict__ b2,
                        float* __restrict__ out) {
    int i = blockIdx.x * blockDim.x + threadIdx.x;
    if (i < NN) {
        float l0 = ALPHA * V[2 * i + 0] + (ALPHA - 1.0f) * Z1[2 * i + 0] - Z2[2 * i + 0] + b2[0];
        float l1 = ALPHA * V[2 * i + 1] + (ALPHA - 1.0f) * Z1[2 * i + 1] - Z2[2 * i + 1] + b2[1];
        float m = fmaxf(l0, l1);
        float lse = m + logf(expf(l0 - m) + expf(l1 - m));
        out[2 * i + 0] = l0 - lse;
        out[2 * i + 1] = l1 - lse;
    }
}

// ---------------- launcher --------------------------------------------------
extern "C" void kernel_launch(void* const* d_in, const int* in_sizes, int n_in,
                              void* d_out, int out_size) {
    const float *x = nullptr, *adj = nullptr, *W1 = nullptr, *W2 = nullptr, *b2 = nullptr;
    for (int i = 0; i < n_in; i++) {
        switch (in_sizes[i]) {
            case NN * NFEAT:             x   = (const float*)d_in[i]; break;
            case (int)((size_t)NN * NN): adj = (const float*)d_in[i]; break;
            case NFEAT * NHID:           W1  = (const float*)d_in[i]; break;
            case NHID * NCLS:            W2  = (const float*)d_in[i]; break;
            case NCLS:                   b2  = (const float*)d_in[i]; break;
        }
    }
    float* out = (float*)d_out;

    Scratch* s = nullptr;
    cudaGetSymbolAddress((void**)&s, g_s);
    float* adjt = nullptr;
    cudaGetSymbolAddress((void**)&adjt, g_adjt);

    // 1) degree vectors + tf32 copy of adj
    k_rowsum<<<NN, 256>>>(adj, s->rowsum);
    k_zero<<<(NN + 255) / 256, 256>>>(s->colsum, NN);
    k_colsum_cvt<<<dim3(NN / 256, NN / 128), 256>>>(adj, adjt, s->colsum);
    k_rsqrt<<<(NN + 255) / 256, 256>>>(s->rowsum, s->colsum, s->drow, s->dcol);

    // 2) M = x @ W1 (fp32)
    k_sgemm<<<dim3(NHID / BN, NN / BM), 256>>>(x, W1, s->M, NHID, NFEAT);

    // 3) Y1 = DAD @ M ; Y2 = DAD @ Y1  (tensor-core TF32)
    k_prepB<<<(NN * NHID + 255) / 256, 256>>>(s->M, s->dcol, s->Bt);
    k_mma_dad<<<dim3(NHID / 128, NN / 128), 128>>>(adjt, s->Bt, s->Y1, s->drow);
    k_prepB<<<(NN * NHID + 255) / 256, 256>>>(s->Y1, s->dcol, s->Bt);
    k_mma_dad<<<dim3(NHID / 128, NN / 128), 128>>>(adjt, s->Bt, s->Y2, s->drow);

    // 4) H = relu(a*M + (a-1)*Y1 - Y2)
    k_combineH<<<(NN * NHID / 4 + 255) / 256, 256>>>(s->M, s->Y1, s->Y2, s->Hh);

    // 5) V = H @ W2
    k_hw2<<<NN / 8, 256>>>(s->Hh, W2, s->V);

    // 6) Z1 = DAD @ V ; Z2 = DAD @ Z1 (fp32, exact)
    k_adjmv2<<<NN, 256>>>(adj, s->V, s->drow, s->dcol, s->Z1);
    k_adjmv2<<<NN, 256>>>(adj, s->Z1, s->drow, s->dcol, s->Z2);

    // 7) logits + log_softmax
    k_final<<<(NN + 255) / 256, 256>>>(s->V, s->Z1, s->Z2, b2, out);
}

// round 6
// speedup vs baseline: 3.2461x; 1.1006x over previous
#include <cuda_runtime.h>
#include <cuda_bf16.h>
#include <math.h>
#include <stdint.h>

#define NN    8192
#define NFEAT 512
#define NHID  256
#define NCLS  2
#define ALPHA 0.5f

// ---------------- scratch (device globals; no allocation allowed) ----------
struct Scratch {
    float rowsum[NN];
    float colsum[NN];            // must stay adjacent to rowsum (zeroed together)
    float drow[NN];
    float dcol[NN];
    float M  [NN * NHID];        // x @ W1  (tf32)
    float Y1 [NN * NHID];        // DAD @ M
    float Y2 [NN * NHID];        // DAD @ Y1
    float xt [NN * NFEAT];       // rna(x)
    float W1r[NFEAT * NHID];     // rna(W1)
    float V [NN * NCLS];
    float Z1[NN * NCLS];
    float Z2[NN * NCLS];
};
__device__ Scratch g_s;
__device__ __align__(16) __nv_bfloat16 g_adjb[(size_t)NN * NN];  // bf16 adj
__device__ __align__(16) __nv_bfloat16 g_Bb[(size_t)NHID * NN];  // B^T operand (n-major)

// ---------------- PTX helpers ----------------------------------------------
__device__ __forceinline__ float to_tf32(float x) {
    float y;
    asm("cvt.rna.tf32.f32 %0, %1;" : "=f"(y) : "f"(x));
    return y;
}

__device__ __forceinline__ void cp_async16(uint32_t saddr, const void* gsrc) {
    asm volatile("cp.async.cg.shared.global [%0], [%1], 16;\n" :: "r"(saddr), "l"(gsrc));
}
#define CP_COMMIT()  asm volatile("cp.async.commit_group;\n" ::: "memory")
#define CP_WAIT(n)   asm volatile("cp.async.wait_group %0;\n" :: "n"(n) : "memory")

__device__ __forceinline__ void ldsm4(uint32_t& r0, uint32_t& r1, uint32_t& r2,
                                      uint32_t& r3, uint32_t addr) {
    asm volatile("ldmatrix.sync.aligned.m8n8.x4.shared.b16 {%0,%1,%2,%3}, [%4];"
                 : "=r"(r0), "=r"(r1), "=r"(r2), "=r"(r3) : "r"(addr));
}

__device__ __forceinline__ void mma_bf16(float* d, const uint32_t* a, const uint32_t* b) {
    asm volatile(
        "mma.sync.aligned.m16n8k16.row.col.f32.bf16.bf16.f32 "
        "{%0,%1,%2,%3}, {%4,%5,%6,%7}, {%8,%9}, {%0,%1,%2,%3};"
        : "+f"(d[0]), "+f"(d[1]), "+f"(d[2]), "+f"(d[3])
        : "r"(a[0]), "r"(a[1]), "r"(a[2]), "r"(a[3]), "r"(b[0]), "r"(b[1]));
}

__device__ __forceinline__ void mma_tf32(float* d, const float* a, const float* b) {
    uint32_t a0 = __float_as_uint(a[0]), a1 = __float_as_uint(a[1]);
    uint32_t a2 = __float_as_uint(a[2]), a3 = __float_as_uint(a[3]);
    uint32_t b0 = __float_as_uint(b[0]), b1 = __float_as_uint(b[1]);
    asm volatile(
        "mma.sync.aligned.m16n8k8.row.col.f32.tf32.tf32.f32 "
        "{%0,%1,%2,%3}, {%4,%5,%6,%7}, {%8,%9}, {%0,%1,%2,%3};"
        : "+f"(d[0]), "+f"(d[1]), "+f"(d[2]), "+f"(d[3])
        : "r"(a0), "r"(a1), "r"(a2), "r"(a3), "r"(b0), "r"(b1));
}

// ---------------- degree sums + bf16 conversion (single pass over adj) ------
__global__ void k_zero(float* __restrict__ p, int n) {
    int i = blockIdx.x * blockDim.x + threadIdx.x;
    if (i < n) p[i] = 0.0f;
}

__global__ void __launch_bounds__(256) k_sums_cvt(const float* __restrict__ adj,
                                                  __nv_bfloat16* __restrict__ adjb,
                                                  float* __restrict__ rowsum,
                                                  float* __restrict__ colsum) {
    int lane = threadIdx.x & 31;
    int c0 = blockIdx.x * 1024 + threadIdx.x * 4;
    size_t r0 = (size_t)blockIdx.y * 128;
    float c4[4] = {0, 0, 0, 0};
    for (int r = 0; r < 128; r++) {
        size_t idx = (r0 + r) * NN + c0;
        float4 v = *(const float4*)(adj + idx);
        c4[0] += v.x; c4[1] += v.y; c4[2] += v.z; c4[3] += v.w;
        __nv_bfloat162 p0 = __floats2bfloat162_rn(v.x, v.y);
        __nv_bfloat162 p1 = __floats2bfloat162_rn(v.z, v.w);
        uint2 pk;
        pk.x = *reinterpret_cast<uint32_t*>(&p0);
        pk.y = *reinterpret_cast<uint32_t*>(&p1);
        *reinterpret_cast<uint2*>(adjb + idx) = pk;
        float w = v.x + v.y + v.z + v.w;
#pragma unroll
        for (int o = 16; o > 0; o >>= 1) w += __shfl_down_sync(0xffffffffu, w, o);
        if (lane == 0) atomicAdd(&rowsum[r0 + r], w);
    }
#pragma unroll
    for (int q = 0; q < 4; q++) atomicAdd(&colsum[c0 + q], c4[q]);
}

__global__ void k_rsqrt(const float* __restrict__ rowsum, const float* __restrict__ colsum,
                        float* __restrict__ drow, float* __restrict__ dcol) {
    int i = blockIdx.x * blockDim.x + threadIdx.x;
    if (i < NN) {
        float r = rowsum[i];
        float c = colsum[i];
        drow[i] = (r > 0.0f) ? rsqrtf(r) : 0.0f;
        dcol[i] = (c > 0.0f) ? rsqrtf(c) : 0.0f;
    }
}

// ---------------- operand preps ---------------------------------------------
__global__ void k_rna_copy(const float* __restrict__ src, float* __restrict__ dst, int n4) {
    int i = blockIdx.x * blockDim.x + threadIdx.x;
    if (i < n4) {
        float4 v = ((const float4*)src)[i];
        float4 t;
        t.x = to_tf32(v.x); t.y = to_tf32(v.y); t.z = to_tf32(v.z); t.w = to_tf32(v.w);
        ((float4*)dst)[i] = t;
    }
}

// dst[c][r] = bf16(scale[r] * src[r][c]);  src: R x Cc fp32, dst: Cc x R bf16
__global__ void __launch_bounds__(256) k_transpose_bf(const float* __restrict__ src,
                                                      __nv_bfloat16* __restrict__ dst,
                                                      int R, int Cc,
                                                      const float* __restrict__ scale) {
    __shared__ float t[32][33];
    int r0 = blockIdx.y * 32;
    int c0 = blockIdx.x * 32;
    int x = threadIdx.x & 31;
    int y = threadIdx.x >> 5;
#pragma unroll
    for (int j = 0; j < 32; j += 8) {
        int r = r0 + y + j;
        t[y + j][x] = src[(size_t)r * Cc + c0 + x] * scale[r];
    }
    __syncthreads();
#pragma unroll
    for (int j = 0; j < 32; j += 8) {
        int c = c0 + y + j;
        dst[(size_t)c * R + r0 + x] = __float2bfloat16_rn(t[x][y + j]);
    }
}

// ---------------- bf16 tensor-core GEMM: C = rowscale ⊙ (A @ B^T_stored) ----
// A: [8192 x K] bf16 row-major; B: [256 x K] bf16 row-major (already B^T).
// C: fp32 [8192 x 256]. Tile 128x128, BK=32, 8 warps (4x2), 3-stage cp.async.
#define GBK 32
#define ROWB 80                      // 64B data + 16B pad per 32-half row
#define G_STAGE (256 * ROWB)         // A rows 0..127, B rows 128..255
#define G_SMEM (3 * G_STAGE)

__global__ void __launch_bounds__(256)
k_bf16_gemm(const __nv_bfloat16* __restrict__ A, const __nv_bfloat16* __restrict__ B,
            float* __restrict__ C, const float* __restrict__ rowscale, int K) {
    extern __shared__ char smem[];
    uint32_t sb = (uint32_t)__cvta_generic_to_shared(smem);
    int tid = threadIdx.x;
    int w = tid >> 5, lane = tid & 31;
    int wm0 = (w >> 1) * 32;         // warp m-origin within 128
    int wn0 = (w & 1) * 64;          // warp n-origin within 128
    int bx = blockIdx.x, by = blockIdx.y;

    const __nv_bfloat16* Ag = A + (size_t)by * 128 * K;
    const __nv_bfloat16* Bg = B + (size_t)bx * 128 * K;

    float acc[2][8][4];
#pragma unroll
    for (int mt = 0; mt < 2; mt++)
#pragma unroll
        for (int nt = 0; nt < 8; nt++)
#pragma unroll
            for (int f = 0; f < 4; f++) acc[mt][nt][f] = 0.0f;

    auto load_stage = [&](int buf, int k0) {
        uint32_t base = sb + buf * G_STAGE;
#pragma unroll
        for (int j = 0; j < 4; j++) {
            int cc = j * 256 + tid;      // 0..1023 chunks of 16B
            int row = cc >> 2;           // 0..255
            int ch = cc & 3;
            const __nv_bfloat16* g =
                (row < 128 ? Ag + (size_t)row * K : Bg + (size_t)(row - 128) * K)
                + k0 + ch * 8;
            cp_async16(base + row * ROWB + ch * 16, g);
        }
    };

    int nK = K / GBK;
    load_stage(0, 0); CP_COMMIT();
    load_stage(1, GBK); CP_COMMIT();

    int buf = 0;
#pragma unroll 1
    for (int i = 0; i < nK; i++) {
        CP_WAIT(1);
        __syncthreads();
        if (i + 2 < nK) load_stage((i + 2) % 3, (i + 2) * GBK);
        CP_COMMIT();      // empty group near the tail keeps the count invariant

        uint32_t sA = sb + buf * G_STAGE;
        uint32_t sB = sA + 128 * ROWB;
#pragma unroll
        for (int ks = 0; ks < 2; ks++) {
            int kc = ks * 2;   // 16B-chunk base within row (0 or 2)
            uint32_t a[2][4];
#pragma unroll
            for (int mt = 0; mt < 2; mt++) {
                uint32_t addr = sA + (wm0 + mt * 16 + (lane & 15)) * ROWB
                              + (kc + (lane >> 4)) * 16;
                ldsm4(a[mt][0], a[mt][1], a[mt][2], a[mt][3], addr);
            }
            uint32_t bfr[8][2];
#pragma unroll
            for (int j = 0; j < 4; j++) {
                uint32_t addr = sB
                    + (wn0 + j * 16 + (lane & 7) + ((lane >> 4) << 3)) * ROWB
                    + (kc + ((lane >> 3) & 1)) * 16;
                uint32_t r0, r1, r2, r3;
                ldsm4(r0, r1, r2, r3, addr);
                bfr[2 * j][0] = r0; bfr[2 * j][1] = r1;
                bfr[2 * j + 1][0] = r2; bfr[2 * j + 1][1] = r3;
            }
#pragma unroll
            for (int mt = 0; mt < 2; mt++)
#pragma unroll
                for (int nt = 0; nt < 8; nt++)
                    mma_bf16(acc[mt][nt], a[mt], bfr[nt]);
        }
        buf = (buf + 1) % 3;
    }

    int g = lane >> 2, q = lane & 3;
#pragma unroll
    for (int mt = 0; mt < 2; mt++) {
        int r0 = by * 128 + wm0 + mt * 16 + g;
        float rs0 = rowscale ? rowscale[r0] : 1.0f;
        float rs1 = rowscale ? rowscale[r0 + 8] : 1.0f;
#pragma unroll
        for (int nt = 0; nt < 8; nt++) {
            int cc = bx * 128 + wn0 + nt * 8 + 2 * q;
            float2 v0 = make_float2(acc[mt][nt][0] * rs0, acc[mt][nt][1] * rs0);
            float2 v1 = make_float2(acc[mt][nt][2] * rs1, acc[mt][nt][3] * rs1);
            *(float2*)(C + (size_t)r0 * NHID + cc) = v0;
            *(float2*)(C + (size_t)(r0 + 8) * NHID + cc) = v1;
        }
    }
}

// ---------------- tf32 tensor-core GEMM (x @ W1; validated in R4) -----------
#define MT_BK 16
#define AS_STRIDE 20
#define BS_STRIDE 136

__global__ void __launch_bounds__(128) k_mma_tf32(const float* __restrict__ A,
                                                  const float* __restrict__ B,
                                                  float* __restrict__ C,
                                                  const float* __restrict__ rowscale,
                                                  int K) {
    __shared__ float As[2][128 * AS_STRIDE];
    __shared__ float Bs[2][MT_BK * BS_STRIDE];

    int tid = threadIdx.x;
    int wid = tid >> 5, lane = tid & 31;
    int wm0 = (wid >> 1) * 64;
    int wn0 = (wid & 1) * 64;
    int bx = blockIdx.x, by = blockIdx.y;

    const float* Ag = A + (size_t)by * 128 * K;
    const float* Bg = B + (size_t)bx * 128;

    float acc[4][8][4];
#pragma unroll
    for (int mt = 0; mt < 4; mt++)
#pragma unroll
        for (int nt = 0; nt < 8; nt++)
#pragma unroll
            for (int f = 0; f < 4; f++) acc[mt][nt][f] = 0.0f;

    int g = lane >> 2;
    int q = lane & 3;

    auto loadA = [&](int buf, int k0) {
#pragma unroll
        for (int i = 0; i < 4; i++) {
            int c = i * 128 + tid;
            int row = c >> 2;
            int coff = (c & 3) * 4;
            uint32_t s = (uint32_t)__cvta_generic_to_shared(
                &As[buf][row * AS_STRIDE + coff]);
            cp_async16(s, Ag + (size_t)row * K + k0 + coff);
        }
    };
    auto loadB = [&](int buf, int k0) {
#pragma unroll
        for (int i = 0; i < 4; i++) {
            int c = i * 128 + tid;
            int kr = c >> 5;
            int coff = (c & 31) * 4;
            uint32_t s = (uint32_t)__cvta_generic_to_shared(
                &Bs[buf][kr * BS_STRIDE + coff]);
            cp_async16(s, Bg + (size_t)(k0 + kr) * NHID + coff);
        }
    };

    loadA(0, 0);
    loadB(0, 0);
    CP_COMMIT();

    int buf = 0;
#pragma unroll 1
    for (int k0 = 0; k0 < K; k0 += MT_BK) {
        if (k0 + MT_BK < K) {
            loadA(buf ^ 1, k0 + MT_BK);
            loadB(buf ^ 1, k0 + MT_BK);
            CP_COMMIT();
            CP_WAIT(1);
        } else {
            CP_WAIT(0);
        }
        __syncthreads();

#pragma unroll
        for (int ks = 0; ks < 2; ks++) {
            int kb = ks * 8;
            float afr[4][4];
#pragma unroll
            for (int mt = 0; mt < 4; mt++) {
                int r = wm0 + mt * 16 + g;
                afr[mt][0] = As[buf][r * AS_STRIDE + kb + q];
                afr[mt][1] = As[buf][(r + 8) * AS_STRIDE + kb + q];
                afr[mt][2] = As[buf][r * AS_STRIDE + kb + q + 4];
                afr[mt][3] = As[buf][(r + 8) * AS_STRIDE + kb + q + 4];
            }
            float bfr[8][2];
#pragma unroll
            for (int nt = 0; nt < 8; nt++) {
                int col = wn0 + nt * 8 + g;
                bfr[nt][0] = Bs[buf][(kb + q) * BS_STRIDE + col];
                bfr[nt][1] = Bs[buf][(kb + q + 4) * BS_STRIDE + col];
            }
#pragma unroll
            for (int mt = 0; mt < 4; mt++)
#pragma unroll
                for (int nt = 0; nt < 8; nt++)
                    mma_tf32(acc[mt][nt], afr[mt], bfr[nt]);
        }
        __syncthreads();
        buf ^= 1;
    }

#pragma unroll
    for (int mt = 0; mt < 4; mt++) {
        int r0 = by * 128 + wm0 + mt * 16 + g;
        float rs0 = rowscale ? rowscale[r0] : 1.0f;
        float rs1 = rowscale ? rowscale[r0 + 8] : 1.0f;
#pragma unroll
        for (int nt = 0; nt < 8; nt++) {
            int cc = bx * 128 + wn0 + nt * 8 + q * 2;
            float2 v0 = make_float2(acc[mt][nt][0] * rs0, acc[mt][nt][1] * rs0);
            float2 v1 = make_float2(acc[mt][nt][2] * rs1, acc[mt][nt][3] * rs1);
            *(float2*)(C + (size_t)r0 * NHID + cc) = v0;
            *(float2*)(C + (size_t)(r0 + 8) * NHID + cc) = v1;
        }
    }
}

// ---------------- fused H + H@W2  (one warp per row) -------------------------
__global__ void __launch_bounds__(256) k_combineV(const float* __restrict__ M,
                                                  const float* __restrict__ Y1,
                                                  const float* __restrict__ Y2,
                                                  const float* __restrict__ W2,
                                                  float* __restrict__ V) {
    int warp = threadIdx.x >> 5;
    int lane = threadIdx.x & 31;
    int row = blockIdx.x * 8 + warp;
    size_t off = (size_t)row * NHID;
    float a0 = 0.0f, a1 = 0.0f;
#pragma unroll
    for (int j = lane; j < NHID; j += 32) {
        float h = fmaxf(ALPHA * M[off + j] + (ALPHA - 1.0f) * Y1[off + j] - Y2[off + j],
                        0.0f);
        a0 = fmaf(h, __ldg(&W2[2 * j + 0]), a0);
        a1 = fmaf(h, __ldg(&W2[2 * j + 1]), a1);
    }
#pragma unroll
    for (int o = 16; o > 0; o >>= 1) {
        a0 += __shfl_down_sync(0xffffffffu, a0, o);
        a1 += __shfl_down_sync(0xffffffffu, a1, o);
    }
    if (lane == 0) {
        V[2 * row + 0] = a0;
        V[2 * row + 1] = a1;
    }
}

// ---------------- adj(bf16) width-2 matvec: out = drow ⊙ (adjb @ (dcol ⊙ v)) -
__global__ void __launch_bounds__(256) k_adjmv2_bf(const __nv_bfloat16* __restrict__ adjb,
                                                   const float* __restrict__ v,
                                                   const float* __restrict__ drow,
                                                   const float* __restrict__ dcol,
                                                   float* __restrict__ out) {
    int row = blockIdx.x;
    const __nv_bfloat16* a = adjb + (size_t)row * NN;
    float a0 = 0.0f, a1 = 0.0f;
    for (int j = threadIdx.x * 8; j < NN; j += 256 * 8) {
        uint4 pk = *(const uint4*)(a + j);
        float2 f0 = __bfloat1622float2(*reinterpret_cast<__nv_bfloat162*>(&pk.x));
        float2 f1 = __bfloat1622float2(*reinterpret_cast<__nv_bfloat162*>(&pk.y));
        float2 f2 = __bfloat1622float2(*reinterpret_cast<__nv_bfloat162*>(&pk.z));
        float2 f3 = __bfloat1622float2(*reinterpret_cast<__nv_bfloat162*>(&pk.w));
        float4 d0 = *(const float4*)(dcol + j);
        float4 d1 = *(const float4*)(dcol + j + 4);
        float av[8] = { f0.x * d0.x, f0.y * d0.y, f1.x * d0.z, f1.y * d0.w,
                        f2.x * d1.x, f2.y * d1.y, f3.x * d1.z, f3.y * d1.w };
#pragma unroll
        for (int t = 0; t < 8; t++) {
            a0 = fmaf(av[t], v[2 * (j + t) + 0], a0);
            a1 = fmaf(av[t], v[2 * (j + t) + 1], a1);
        }
    }
    __shared__ float s0[256];
    __shared__ float s1[256];
    s0[threadIdx.x] = a0;
    s1[threadIdx.x] = a1;
    __syncthreads();
    for (int st = 128; st > 0; st >>= 1) {
        if (threadIdx.x < st) {
            s0[threadIdx.x] += s0[threadIdx.x + st];
            s1[threadIdx.x] += s1[threadIdx.x + st];
        }
        __syncthreads();
    }
    if (threadIdx.x == 0) {
        float r = drow[row];
        out[2 * row + 0] = r * s0[0];
        out[2 * row + 1] = r * s1[0];
    }
}

__global__ void k_final(const float* __restrict__ V, const float* __restrict__ Z1,
                        const float* __restrict__ Z2, const float* __restrict__ b2,
                        float* __restrict__ out) {
    int i = blockIdx.x * blockDim.x + threadIdx.x;
    if (i < NN) {
        float l0 = ALPHA * V[2 * i + 0] + (ALPHA - 1.0f) * Z1[2 * i + 0] - Z2[2 * i + 0] + b2[0];
        float l1 = ALPHA * V[2 * i + 1] + (ALPHA - 1.0f) * Z1[2 * i + 1] - Z2[2 * i + 1] + b2[1];
        float m = fmaxf(l0, l1);
        float lse = m + logf(expf(l0 - m) + expf(l1 - m));
        out[2 * i + 0] = l0 - lse;
        out[2 * i + 1] = l1 - lse;
    }
}

// ---------------- launcher --------------------------------------------------
extern "C" void kernel_launch(void* const* d_in, const int* in_sizes, int n_in,
                              void* d_out, int out_size) {
    const float *x = nullptr, *adj = nullptr, *W1 = nullptr, *W2 = nullptr, *b2 = nullptr;
    for (int i = 0; i < n_in; i++) {
        switch (in_sizes[i]) {
            case NN * NFEAT:             x   = (const float*)d_in[i]; break;
            case (int)((size_t)NN * NN): adj = (const float*)d_in[i]; break;
            case NFEAT * NHID:           W1  = (const float*)d_in[i]; break;
            case NHID * NCLS:            W2  = (const float*)d_in[i]; break;
            case NCLS:                   b2  = (const float*)d_in[i]; break;
        }
    }
    float* out = (float*)d_out;

    Scratch* s = nullptr;
    cudaGetSymbolAddress((void**)&s, g_s);
    __nv_bfloat16* adjb = nullptr;
    cudaGetSymbolAddress((void**)&adjb, g_adjb);
    __nv_bfloat16* Bb = nullptr;
    cudaGetSymbolAddress((void**)&Bb, g_Bb);

    cudaFuncSetAttribute(k_bf16_gemm, cudaFuncAttributeMaxDynamicSharedMemorySize, G_SMEM);

    // 1) degree vectors + bf16 adj copy (single pass over adj)
    k_zero<<<(2 * NN + 255) / 256, 256>>>(s->rowsum, 2 * NN);
    k_sums_cvt<<<dim3(NN / 1024, NN / 128), 256>>>(adj, adjb, s->rowsum, s->colsum);
    k_rsqrt<<<(NN + 255) / 256, 256>>>(s->rowsum, s->colsum, s->drow, s->dcol);

    // 2) M = x @ W1 (tf32 tensor cores)
    k_rna_copy<<<(NN * NFEAT / 4 + 255) / 256, 256>>>(x, s->xt, NN * NFEAT / 4);
    k_rna_copy<<<(NFEAT * NHID / 4 + 255) / 256, 256>>>(W1, s->W1r, NFEAT * NHID / 4);
    k_mma_tf32<<<dim3(2, NN / 128), 128>>>(s->xt, s->W1r, s->M, nullptr, NFEAT);

    // 3) Y1 = DAD @ M ; Y2 = DAD @ Y1 (bf16 tensor cores; dcol fused into B prep,
    //    drow fused into epilogue)
    k_transpose_bf<<<dim3(NHID / 32, NN / 32), 256>>>(s->M, Bb, NN, NHID, s->dcol);
    k_bf16_gemm<<<dim3(2, NN / 128), 256, G_SMEM>>>(adjb, Bb, s->Y1, s->drow, NN);
    k_transpose_bf<<<dim3(NHID / 32, NN / 32), 256>>>(s->Y1, Bb, NN, NHID, s->dcol);
    k_bf16_gemm<<<dim3(2, NN / 128), 256, G_SMEM>>>(adjb, Bb, s->Y2, s->drow, NN);

    // 4+5) V = relu(a*M + (a-1)*Y1 - Y2) @ W2  (fused)
    k_combineV<<<NN / 8, 256>>>(s->M, s->Y1, s->Y2, W2, s->V);

    // 6) Z1 = DAD @ V ; Z2 = DAD @ Z1 (bf16 adj)
    k_adjmv2_bf<<<NN, 256>>>(adjb, s->V, s->drow, s->dcol, s->Z1);
    k_adjmv2_bf<<<NN, 256>>>(adjb, s->Z1, s->drow, s->dcol, s->Z2);

    // 7) logits + log_softmax
    k_final<<<(NN + 255) / 256, 256>>>(s->V, s->Z1, s->Z2, b2, out);
}

// round 7
// speedup vs baseline: 3.3250x; 1.0243x over previous
#include <cuda_runtime.h>
#include <cuda_bf16.h>
#include <math.h>
#include <stdint.h>

#define NN    8192
#define NFEAT 512
#define NHID  256
#define NCLS  2
#define ALPHA 0.5f

// ---------------- scratch (device globals; no allocation allowed) ----------
struct Scratch {
    float rowsum[NN];
    float colsum[NN];            // must stay adjacent to rowsum (zeroed together)
    float M  [NN * NHID];        // x @ W1  (tf32)
    float Y1 [NN * NHID];        // DAD @ M
    float Y2 [NN * NHID];        // DAD @ Y1
    float V [NN * NCLS];
    float Z1[NN * NCLS];
    float Z2[NN * NCLS];
};
__device__ Scratch g_s;
__device__ __align__(16) __nv_bfloat16 g_adjb[(size_t)NN * NN];  // bf16 adj
__device__ __align__(16) __nv_bfloat16 g_Bb[(size_t)NHID * NN];  // B^T operand (n-major)

// ---------------- PTX helpers ----------------------------------------------
__device__ __forceinline__ float to_tf32(float x) {
    float y;
    asm("cvt.rna.tf32.f32 %0, %1;" : "=f"(y) : "f"(x));
    return y;
}

__device__ __forceinline__ void cp_async16(uint32_t saddr, const void* gsrc) {
    asm volatile("cp.async.cg.shared.global [%0], [%1], 16;\n" :: "r"(saddr), "l"(gsrc));
}
#define CP_COMMIT()  asm volatile("cp.async.commit_group;\n" ::: "memory")
#define CP_WAIT(n)   asm volatile("cp.async.wait_group %0;\n" :: "n"(n) : "memory")

__device__ __forceinline__ void ldsm4(uint32_t& r0, uint32_t& r1, uint32_t& r2,
                                      uint32_t& r3, uint32_t addr) {
    asm volatile("ldmatrix.sync.aligned.m8n8.x4.shared.b16 {%0,%1,%2,%3}, [%4];"
                 : "=r"(r0), "=r"(r1), "=r"(r2), "=r"(r3) : "r"(addr));
}

__device__ __forceinline__ void mma_bf16(float* d, const uint32_t* a, const uint32_t* b) {
    asm volatile(
        "mma.sync.aligned.m16n8k16.row.col.f32.bf16.bf16.f32 "
        "{%0,%1,%2,%3}, {%4,%5,%6,%7}, {%8,%9}, {%0,%1,%2,%3};"
        : "+f"(d[0]), "+f"(d[1]), "+f"(d[2]), "+f"(d[3])
        : "r"(a[0]), "r"(a[1]), "r"(a[2]), "r"(a[3]), "r"(b[0]), "r"(b[1]));
}

__device__ __forceinline__ void mma_tf32(float* d, const float* a, const float* b) {
    uint32_t a0 = __float_as_uint(a[0]), a1 = __float_as_uint(a[1]);
    uint32_t a2 = __float_as_uint(a[2]), a3 = __float_as_uint(a[3]);
    uint32_t b0 = __float_as_uint(b[0]), b1 = __float_as_uint(b[1]);
    asm volatile(
        "mma.sync.aligned.m16n8k8.row.col.f32.tf32.tf32.f32 "
        "{%0,%1,%2,%3}, {%4,%5,%6,%7}, {%8,%9}, {%0,%1,%2,%3};"
        : "+f"(d[0]), "+f"(d[1]), "+f"(d[2]), "+f"(d[3])
        : "r"(a0), "r"(a1), "r"(a2), "r"(a3), "r"(b0), "r"(b1));
}

__device__ __forceinline__ float inv_sqrt_pos(float v) {
    return (v > 0.0f) ? rsqrtf(v) : 0.0f;
}

// ---------------- degree sums + bf16 conversion (single pass over adj) ------
__global__ void k_zero(float* __restrict__ p, int n) {
    int i = blockIdx.x * blockDim.x + threadIdx.x;
    if (i < n) p[i] = 0.0f;
}

__global__ void __launch_bounds__(256) k_sums_cvt(const float* __restrict__ adj,
                                                  __nv_bfloat16* __restrict__ adjb,
                                                  float* __restrict__ rowsum,
                                                  float* __restrict__ colsum) {
    int lane = threadIdx.x & 31;
    int c0 = blockIdx.x * 1024 + threadIdx.x * 4;
    size_t r0 = (size_t)blockIdx.y * 128;
    float c4[4] = {0, 0, 0, 0};
    for (int r = 0; r < 128; r++) {
        size_t idx = (r0 + r) * NN + c0;
        float4 v = *(const float4*)(adj + idx);
        c4[0] += v.x; c4[1] += v.y; c4[2] += v.z; c4[3] += v.w;
        __nv_bfloat162 p0 = __floats2bfloat162_rn(v.x, v.y);
        __nv_bfloat162 p1 = __floats2bfloat162_rn(v.z, v.w);
        uint2 pk;
        pk.x = *reinterpret_cast<uint32_t*>(&p0);
        pk.y = *reinterpret_cast<uint32_t*>(&p1);
        *reinterpret_cast<uint2*>(adjb + idx) = pk;
        float w = v.x + v.y + v.z + v.w;
#pragma unroll
        for (int o = 16; o > 0; o >>= 1) w += __shfl_down_sync(0xffffffffu, w, o);
        if (lane == 0) atomicAdd(&rowsum[r0 + r], w);
    }
#pragma unroll
    for (int q = 0; q < 4; q++) atomicAdd(&colsum[c0 + q], c4[q]);
}

// ---------------- operand prep: transpose + dcol + bf16 ---------------------
// dst[c][r] = bf16(rsqrt(colsum[r]) * src[r][c]);  src: R x Cc fp32
__global__ void __launch_bounds__(256) k_transpose_bf(const float* __restrict__ src,
                                                      __nv_bfloat16* __restrict__ dst,
                                                      int R, int Cc,
                                                      const float* __restrict__ colsum) {
    __shared__ float t[32][33];
    int r0 = blockIdx.y * 32;
    int c0 = blockIdx.x * 32;
    int x = threadIdx.x & 31;
    int y = threadIdx.x >> 5;
#pragma unroll
    for (int j = 0; j < 32; j += 8) {
        int r = r0 + y + j;
        t[y + j][x] = src[(size_t)r * Cc + c0 + x] * inv_sqrt_pos(colsum[r]);
    }
    __syncthreads();
#pragma unroll
    for (int j = 0; j < 32; j += 8) {
        int c = c0 + y + j;
        dst[(size_t)c * R + r0 + x] = __float2bfloat16_rn(t[x][y + j]);
    }
}

// ---------------- bf16 tensor-core GEMM: C = drow ⊙ (A @ B^T_stored) --------
// A: [8192 x K] bf16 row-major; B: [256 x K] bf16 row-major (already B^T).
// C: fp32 [8192 x 256]. Tile 64x128, BK=32, 8 warps (2x4), 4-stage cp.async.
#define GBK 32
#define ROWB 80                       // 64B data + 16B pad per 32-half row
#define G_NROWS 192                   // A rows 0..63, B rows 64..191
#define G_STAGE (G_NROWS * ROWB)      // 15360
#define G_SMEM (4 * G_STAGE)          // 61440

__global__ void __launch_bounds__(256)
k_bf16_gemm(const __nv_bfloat16* __restrict__ A, const __nv_bfloat16* __restrict__ B,
            float* __restrict__ C, const float* __restrict__ rowsum, int K) {
    extern __shared__ char smem[];
    uint32_t sb = (uint32_t)__cvta_generic_to_shared(smem);
    int tid = threadIdx.x;
    int w = tid >> 5, lane = tid & 31;
    int wm0 = (w >> 2) * 32;          // 0 / 32
    int wn0 = (w & 3) * 32;           // 0 / 32 / 64 / 96
    int bx = blockIdx.x, by = blockIdx.y;

    const __nv_bfloat16* Ag = A + (size_t)by * 64 * K;
    const __nv_bfloat16* Bg = B + (size_t)bx * 128 * K;

    float acc[2][4][4];
#pragma unroll
    for (int mt = 0; mt < 2; mt++)
#pragma unroll
        for (int nt = 0; nt < 4; nt++)
#pragma unroll
            for (int f = 0; f < 4; f++) acc[mt][nt][f] = 0.0f;

    // 768 16B-chunks per stage (192 rows x 4 chunks) = 3 per thread exactly
    auto load_stage = [&](int buf, int k0) {
        uint32_t base = sb + buf * G_STAGE;
#pragma unroll
        for (int j = 0; j < 3; j++) {
            int idx = j * 256 + tid;
            int row = idx >> 2;
            int ch = idx & 3;
            const __nv_bfloat16* g =
                (row < 64 ? Ag + (size_t)row * K : Bg + (size_t)(row - 64) * K)
                + k0 + ch * 8;
            cp_async16(base + row * ROWB + ch * 16, g);
        }
    };

    int nK = K / GBK;
    load_stage(0, 0); CP_COMMIT();
    load_stage(1, GBK); CP_COMMIT();
    load_stage(2, 2 * GBK); CP_COMMIT();

#pragma unroll 1
    for (int i = 0; i < nK; i++) {
        CP_WAIT(2);
        __syncthreads();
        if (i + 3 < nK) load_stage((i + 3) & 3, (i + 3) * GBK);
        CP_COMMIT();      // empty group near the tail keeps the count invariant

        uint32_t sA = sb + (i & 3) * G_STAGE;
        uint32_t sB = sA + 64 * ROWB;
#pragma unroll
        for (int ks = 0; ks < 2; ks++) {
            int kc = ks * 2;   // 16B-chunk base within row (0 or 2)
            uint32_t a[2][4];
#pragma unroll
            for (int mt = 0; mt < 2; mt++) {
                uint32_t addr = sA + (wm0 + mt * 16 + (lane & 15)) * ROWB
                              + (kc + (lane >> 4)) * 16;
                ldsm4(a[mt][0], a[mt][1], a[mt][2], a[mt][3], addr);
            }
            uint32_t bfr[4][2];
#pragma unroll
            for (int j = 0; j < 2; j++) {
                uint32_t addr = sB
                    + (wn0 + j * 16 + (lane & 7) + ((lane >> 4) << 3)) * ROWB
                    + (kc + ((lane >> 3) & 1)) * 16;
                uint32_t r0, r1, r2, r3;
                ldsm4(r0, r1, r2, r3, addr);
                bfr[2 * j][0] = r0; bfr[2 * j][1] = r1;
                bfr[2 * j + 1][0] = r2; bfr[2 * j + 1][1] = r3;
            }
#pragma unroll
            for (int mt = 0; mt < 2; mt++)
#pragma unroll
                for (int nt = 0; nt < 4; nt++)
                    mma_bf16(acc[mt][nt], a[mt], bfr[nt]);
        }
    }

    int g = lane >> 2, q = lane & 3;
#pragma unroll
    for (int mt = 0; mt < 2; mt++) {
        int r0 = by * 64 + wm0 + mt * 16 + g;
        float rs0 = rowsum ? inv_sqrt_pos(rowsum[r0]) : 1.0f;
        float rs1 = rowsum ? inv_sqrt_pos(rowsum[r0 + 8]) : 1.0f;
#pragma unroll
        for (int nt = 0; nt < 4; nt++) {
            int cc = bx * 128 + wn0 + nt * 8 + 2 * q;
            float2 v0 = make_float2(acc[mt][nt][0] * rs0, acc[mt][nt][1] * rs0);
            float2 v1 = make_float2(acc[mt][nt][2] * rs1, acc[mt][nt][3] * rs1);
            *(float2*)(C + (size_t)r0 * NHID + cc) = v0;
            *(float2*)(C + (size_t)(r0 + 8) * NHID + cc) = v1;
        }
    }
}

// ---------------- tf32 tensor-core GEMM (x @ W1; rna cvt at fragment load) --
#define MT_BK 16
#define AS_STRIDE 20
#define BS_STRIDE 136

__global__ void __launch_bounds__(128) k_mma_tf32(const float* __restrict__ A,
                                                  const float* __restrict__ B,
                                                  float* __restrict__ C,
                                                  int K) {
    __shared__ float As[2][128 * AS_STRIDE];
    __shared__ float Bs[2][MT_BK * BS_STRIDE];

    int tid = threadIdx.x;
    int wid = tid >> 5, lane = tid & 31;
    int wm0 = (wid >> 1) * 64;
    int wn0 = (wid & 1) * 64;
    int bx = blockIdx.x, by = blockIdx.y;

    const float* Ag = A + (size_t)by * 128 * K;
    const float* Bg = B + (size_t)bx * 128;

    float acc[4][8][4];
#pragma unroll
    for (int mt = 0; mt < 4; mt++)
#pragma unroll
        for (int nt = 0; nt < 8; nt++)
#pragma unroll
            for (int f = 0; f < 4; f++) acc[mt][nt][f] = 0.0f;

    int g = lane >> 2;
    int q = lane & 3;

    auto loadA = [&](int buf, int k0) {
#pragma unroll
        for (int i = 0; i < 4; i++) {
            int c = i * 128 + tid;
            int row = c >> 2;
            int coff = (c & 3) * 4;
            uint32_t s = (uint32_t)__cvta_generic_to_shared(
                &As[buf][row * AS_STRIDE + coff]);
            cp_async16(s, Ag + (size_t)row * K + k0 + coff);
        }
    };
    auto loadB = [&](int buf, int k0) {
#pragma unroll
        for (int i = 0; i < 4; i++) {
            int c = i * 128 + tid;
            int kr = c >> 5;
            int coff = (c & 31) * 4;
            uint32_t s = (uint32_t)__cvta_generic_to_shared(
                &Bs[buf][kr * BS_STRIDE + coff]);
            cp_async16(s, Bg + (size_t)(k0 + kr) * NHID + coff);
        }
    };

    loadA(0, 0);
    loadB(0, 0);
    CP_COMMIT();

    int buf = 0;
#pragma unroll 1
    for (int k0 = 0; k0 < K; k0 += MT_BK) {
        if (k0 + MT_BK < K) {
            loadA(buf ^ 1, k0 + MT_BK);
            loadB(buf ^ 1, k0 + MT_BK);
            CP_COMMIT();
            CP_WAIT(1);
        } else {
            CP_WAIT(0);
        }
        __syncthreads();

#pragma unroll
        for (int ks = 0; ks < 2; ks++) {
            int kb = ks * 8;
            float afr[4][4];
#pragma unroll
            for (int mt = 0; mt < 4; mt++) {
                int r = wm0 + mt * 16 + g;
                afr[mt][0] = to_tf32(As[buf][r * AS_STRIDE + kb + q]);
                afr[mt][1] = to_tf32(As[buf][(r + 8) * AS_STRIDE + kb + q]);
                afr[mt][2] = to_tf32(As[buf][r * AS_STRIDE + kb + q + 4]);
                afr[mt][3] = to_tf32(As[buf][(r + 8) * AS_STRIDE + kb + q + 4]);
            }
            float bfr[8][2];
#pragma unroll
            for (int nt = 0; nt < 8; nt++) {
                int col = wn0 + nt * 8 + g;
                bfr[nt][0] = to_tf32(Bs[buf][(kb + q) * BS_STRIDE + col]);
                bfr[nt][1] = to_tf32(Bs[buf][(kb + q + 4) * BS_STRIDE + col]);
            }
#pragma unroll
            for (int mt = 0; mt < 4; mt++)
#pragma unroll
                for (int nt = 0; nt < 8; nt++)
                    mma_tf32(acc[mt][nt], afr[mt], bfr[nt]);
        }
        __syncthreads();
        buf ^= 1;
    }

#pragma unroll
    for (int mt = 0; mt < 4; mt++) {
        int r0 = by * 128 + wm0 + mt * 16 + g;
#pragma unroll
        for (int nt = 0; nt < 8; nt++) {
            int cc = bx * 128 + wn0 + nt * 8 + q * 2;
            float2 v0 = make_float2(acc[mt][nt][0], acc[mt][nt][1]);
            float2 v1 = make_float2(acc[mt][nt][2], acc[mt][nt][3]);
            *(float2*)(C + (size_t)r0 * NHID + cc) = v0;
            *(float2*)(C + (size_t)(r0 + 8) * NHID + cc) = v1;
        }
    }
}

// ---------------- fused H + H@W2  (one warp per row) -------------------------
__global__ void __launch_bounds__(256) k_combineV(const float* __restrict__ M,
                                                  const float* __restrict__ Y1,
                                                  const float* __restrict__ Y2,
                                                  const float* __restrict__ W2,
                                                  float* __restrict__ V) {
    int warp = threadIdx.x >> 5;
    int lane = threadIdx.x & 31;
    int row = blockIdx.x * 8 + warp;
    size_t off = (size_t)row * NHID;
    float a0 = 0.0f, a1 = 0.0f;
#pragma unroll
    for (int j = lane; j < NHID; j += 32) {
        float h = fmaxf(ALPHA * M[off + j] + (ALPHA - 1.0f) * Y1[off + j] - Y2[off + j],
                        0.0f);
        a0 = fmaf(h, __ldg(&W2[2 * j + 0]), a0);
        a1 = fmaf(h, __ldg(&W2[2 * j + 1]), a1);
    }
#pragma unroll
    for (int o = 16; o > 0; o >>= 1) {
        a0 += __shfl_down_sync(0xffffffffu, a0, o);
        a1 += __shfl_down_sync(0xffffffffu, a1, o);
    }
    if (lane == 0) {
        V[2 * row + 0] = a0;
        V[2 * row + 1] = a1;
    }
}

// ---------------- adj(bf16) width-2 matvec ----------------------------------
// out = rsqrt(rowsum) ⊙ (adjb @ (rsqrt(colsum) ⊙ v))
__global__ void __launch_bounds__(256) k_adjmv2_bf(const __nv_bfloat16* __restrict__ adjb,
                                                   const float* __restrict__ v,
                                                   const float* __restrict__ rowsum,
                                                   const float* __restrict__ colsum,
                                                   float* __restrict__ out) {
    int row = blockIdx.x;
    const __nv_bfloat16* a = adjb + (size_t)row * NN;
    float a0 = 0.0f, a1 = 0.0f;
    for (int j = threadIdx.x * 8; j < NN; j += 256 * 8) {
        uint4 pk = *(const uint4*)(a + j);
        float2 f0 = __bfloat1622float2(*reinterpret_cast<__nv_bfloat162*>(&pk.x));
        float2 f1 = __bfloat1622float2(*reinterpret_cast<__nv_bfloat162*>(&pk.y));
        float2 f2 = __bfloat1622float2(*reinterpret_cast<__nv_bfloat162*>(&pk.z));
        float2 f3 = __bfloat1622float2(*reinterpret_cast<__nv_bfloat162*>(&pk.w));
        float4 c0 = *(const float4*)(colsum + j);
        float4 c1 = *(const float4*)(colsum + j + 4);
        float av[8] = { f0.x * inv_sqrt_pos(c0.x), f0.y * inv_sqrt_pos(c0.y),
                        f1.x * inv_sqrt_pos(c0.z), f1.y * inv_sqrt_pos(c0.w),
                        f2.x * inv_sqrt_pos(c1.x), f2.y * inv_sqrt_pos(c1.y),
                        f3.x * inv_sqrt_pos(c1.z), f3.y * inv_sqrt_pos(c1.w) };
#pragma unroll
        for (int t = 0; t < 8; t++) {
            a0 = fmaf(av[t], v[2 * (j + t) + 0], a0);
            a1 = fmaf(av[t], v[2 * (j + t) + 1], a1);
        }
    }
    __shared__ float s0[256];
    __shared__ float s1[256];
    s0[threadIdx.x] = a0;
    s1[threadIdx.x] = a1;
    __syncthreads();
    for (int st = 128; st > 0; st >>= 1) {
        if (threadIdx.x < st) {
            s0[threadIdx.x] += s0[threadIdx.x + st];
            s1[threadIdx.x] += s1[threadIdx.x + st];
        }
        __syncthreads();
    }
    if (threadIdx.x == 0) {
        float r = inv_sqrt_pos(rowsum[row]);
        out[2 * row + 0] = r * s0[0];
        out[2 * row + 1] = r * s1[0];
    }
}

__global__ void k_final(const float* __restrict__ V, const float* __restrict__ Z1,
                        const float* __restrict__ Z2, const float* __restrict__ b2,
                        float* __restrict__ out) {
    int i = blockIdx.x * blockDim.x + threadIdx.x;
    if (i < NN) {
        float l0 = ALPHA * V[2 * i + 0] + (ALPHA - 1.0f) * Z1[2 * i + 0] - Z2[2 * i + 0] + b2[0];
        float l1 = ALPHA * V[2 * i + 1] + (ALPHA - 1.0f) * Z1[2 * i + 1] - Z2[2 * i + 1] + b2[1];
        float m = fmaxf(l0, l1);
        float lse = m + logf(expf(l0 - m) + expf(l1 - m));
        out[2 * i + 0] = l0 - lse;
        out[2 * i + 1] = l1 - lse;
    }
}

// ---------------- launcher --------------------------------------------------
extern "C" void kernel_launch(void* const* d_in, const int* in_sizes, int n_in,
                              void* d_out, int out_size) {
    const float *x = nullptr, *adj = nullptr, *W1 = nullptr, *W2 = nullptr, *b2 = nullptr;
    for (int i = 0; i < n_in; i++) {
        switch (in_sizes[i]) {
            case NN * NFEAT:             x   = (const float*)d_in[i]; break;
            case (int)((size_t)NN * NN): adj = (const float*)d_in[i]; break;
            case NFEAT * NHID:           W1  = (const float*)d_in[i]; break;
            case NHID * NCLS:            W2  = (const float*)d_in[i]; break;
            case NCLS:                   b2  = (const float*)d_in[i]; break;
        }
    }
    float* out = (float*)d_out;

    Scratch* s = nullptr;
    cudaGetSymbolAddress((void**)&s, g_s);
    __nv_bfloat16* adjb = nullptr;
    cudaGetSymbolAddress((void**)&adjb, g_adjb);
    __nv_bfloat16* Bb = nullptr;
    cudaGetSymbolAddress((void**)&Bb, g_Bb);

    cudaFuncSetAttribute(k_bf16_gemm, cudaFuncAttributeMaxDynamicSharedMemorySize, G_SMEM);

    // 1) zero sums
    k_zero<<<(2 * NN + 255) / 256, 256>>>(s->rowsum, 2 * NN);
    // 2) degree sums + bf16 adj copy (single pass over adj)
    k_sums_cvt<<<dim3(NN / 1024, NN / 128), 256>>>(adj, adjb, s->rowsum, s->colsum);
    // 3) M = x @ W1 (tf32 tensor cores, rna cvt in-kernel)
    k_mma_tf32<<<dim3(2, NN / 128), 128>>>(x, W1, s->M, NFEAT);
    // 4) B operand prep (dcol = rsqrt(colsum) fused)
    k_transpose_bf<<<dim3(NHID / 32, NN / 32), 256>>>(s->M, Bb, NN, NHID, s->colsum);
    // 5) Y1 = DAD @ M  (bf16 tensor cores; drow fused)   <-- ncu capture target
    k_bf16_gemm<<<dim3(2, NN / 64), 256, G_SMEM>>>(adjb, Bb, s->Y1, s->rowsum, NN);
    // 6) B operand prep for Y2
    k_transpose_bf<<<dim3(NHID / 32, NN / 32), 256>>>(s->Y1, Bb, NN, NHID, s->colsum);
    // 7) Y2 = DAD @ Y1
    k_bf16_gemm<<<dim3(2, NN / 64), 256, G_SMEM>>>(adjb, Bb, s->Y2, s->rowsum, NN);
    // 8) V = relu(a*M + (a-1)*Y1 - Y2) @ W2  (fused)
    k_combineV<<<NN / 8, 256>>>(s->M, s->Y1, s->Y2, W2, s->V);
    // 9-10) Z1 = DAD @ V ; Z2 = DAD @ Z1 (bf16 adj)
    k_adjmv2_bf<<<NN, 256>>>(adjb, s->V, s->rowsum, s->colsum, s->Z1);
    k_adjmv2_bf<<<NN, 256>>>(adjb, s->Z1, s->rowsum, s->colsum, s->Z2);
    // 11) logits + log_softmax
    k_final<<<(NN + 255) / 256, 256>>>(s->V, s->Z1, s->Z2, b2, out);
}